// round 1
// baseline (speedup 1.0000x reference)
#include <cuda_runtime.h>
#include <math.h>

#define B_ 16
#define Q_ 100
#define G_ 16384
#define T_ 50
#define L_ 21
#define KT 32              // k per smem stage
#define NCHUNK 37          // k-chunks per batch -> grid 37*16 = 592 = 4 * 148
#define NTILES (G_/KT)     // 512 KT-tiles per batch
#define QPAD 100
#define TPAD 60

// ---------------- device scratch (no allocations allowed) ----------------
__device__ float g_Sneg[B_*Q_];
__device__ float g_Ssig[B_*Q_];
__device__ float g_Sm[B_*T_];
__device__ float g_D1[B_*Q_*T_];
__device__ float g_D2[B_*Q_*T_];
__device__ int   g_is64;

// ---------------- f32x2 packed helpers (sm_103a) ----------------
__device__ __forceinline__ unsigned long long dup2(float x) {
    unsigned long long r;
    asm("mov.b64 %0, {%1,%1};" : "=l"(r) : "f"(x));
    return r;
}
__device__ __forceinline__ void fma2(unsigned long long& acc,
                                     unsigned long long a,
                                     unsigned long long b) {
    asm("fma.rn.f32x2 %0, %1, %2, %0;" : "+l"(acc) : "l"(a), "l"(b));
}
__device__ __forceinline__ float2 unpk(unsigned long long v) {
    float2 r;
    asm("mov.b64 {%0,%1}, %2;" : "=f"(r.x), "=f"(r.y) : "l"(v));
    return r;
}

// ---------------- kernel 0: zero scratch + detect label dtype ----------------
__global__ void zero_detect_kernel(const int* __restrict__ labw) {
    int i = blockIdx.x * blockDim.x + threadIdx.x;
    if (i < B_*Q_)    { g_Sneg[i] = 0.f; g_Ssig[i] = 0.f; }
    if (i < B_*T_)    { g_Sm[i] = 0.f; }
    if (i < B_*Q_*T_) { g_D1[i] = 0.f; g_D2[i] = 0.f; }
    if (i == 0) {
        // int64 little-endian: odd 32-bit words are high halves == 0 (labels in [0,21)).
        // int32: odd words are random labels -> essentially never all zero.
        int is64 = 1;
        #pragma unroll 1
        for (int j = 0; j < 64; j++) {
            if (labw[2*j + 1] != 0) { is64 = 0; break; }
        }
        g_is64 = is64;
    }
}

// ---------------- kernel 1: dual split-K GEMM + fused row stats ----------------
// grid = (NCHUNK, B_), block = 128 threads.
// Computes partial dot(x,m) -> g_D1, dot(sigmoid(x),m) -> g_D2, and row sums.
__global__ void __launch_bounds__(128, 2)
pm_main_kernel(const float* __restrict__ xg, const float* __restrict__ mg)
{
    __shared__ float xs[KT * QPAD];   // [k][q]
    __shared__ float ss[KT * QPAD];   // [k][q] sigmoid
    __shared__ float ms[KT * TPAD];   // [k][t-padded-groups]

    const int b   = blockIdx.y;
    const int c   = blockIdx.x;
    const int tid = threadIdx.x;

    // uneven chunk split: 512 tiles over 37 CTAs -> 31 CTAs get 14, 6 get 13
    const int base = NTILES / NCHUNK;             // 13
    const int rem  = NTILES - base * NCHUNK;      // 31
    const int ntile = base + (c < rem ? 1 : 0);
    const int tile0 = c * base + (c < rem ? c : rem);

    // loader row-stat accumulators (slot -> fixed row across stages)
    float aSP[7], aSG[7], aM[4];
    #pragma unroll
    for (int j = 0; j < 7; j++) { aSP[j] = 0.f; aSG[j] = 0.f; }
    #pragma unroll
    for (int j = 0; j < 4; j++) aM[j] = 0.f;

    const int qt = tid / 5;
    const int tt = tid - qt * 5;
    const bool comp = (tid < 125);

    unsigned long long a1[4][5], a2[4][5];
    #pragma unroll
    for (int i = 0; i < 4; i++)
        #pragma unroll
        for (int p = 0; p < 5; p++) { a1[i][p] = 0ull; a2[i][p] = 0ull; }

    for (int st = 0; st < ntile; st++) {
        const int ks = (tile0 + st) * KT;   // absolute g offset of this stage

        // ---- load x tile (and sigmoid), fused softplus/sigmoid row stats ----
        #pragma unroll
        for (int j = 0; j < 7; j++) {
            int s = tid + 128 * j;
            if (s < Q_ * (KT/4)) {
                int row = s >> 3, c4 = s & 7;
                const float4 v = *reinterpret_cast<const float4*>(
                    xg + (size_t)(b * Q_ + row) * G_ + ks + c4 * 4);
                float vv[4] = { v.x, v.y, v.z, v.w };
                #pragma unroll
                for (int u = 0; u < 4; u++) {
                    float x  = vv[u];
                    float e  = __expf(-fabsf(x));
                    float iv = __fdividef(1.f, 1.f + e);
                    float sg = (x >= 0.f) ? iv : (1.f - iv);
                    float sp = fmaxf(x, 0.f) + __logf(1.f + e);
                    int k = c4 * 4 + u;
                    xs[k * QPAD + row] = x;
                    ss[k * QPAD + row] = sg;
                    aSP[j] += sp;
                    aSG[j] += sg;
                }
            }
        }
        // ---- load m tile (padded t groups of 12) ----
        #pragma unroll
        for (int j = 0; j < 4; j++) {
            int s = tid + 128 * j;
            if (s < T_ * (KT/4)) {
                int row = s >> 3, c4 = s & 7;
                const float4 v = *reinterpret_cast<const float4*>(
                    mg + (size_t)(b * T_ + row) * G_ + ks + c4 * 4);
                float vv[4] = { v.x, v.y, v.z, v.w };
                int p = (row / 10) * 12 + (row % 10);
                #pragma unroll
                for (int u = 0; u < 4; u++) {
                    int k = c4 * 4 + u;
                    ms[k * TPAD + p] = vv[u];
                    aM[j] += vv[u];
                }
            }
        }
        __syncthreads();

        // ---- compute: RQ=4 x RT=10 register tile, packed f32x2 FMAs ----
        if (comp) {
            #pragma unroll 4
            for (int k = 0; k < KT; k++) {
                const float4 xv = *reinterpret_cast<const float4*>(xs + k * QPAD + qt * 4);
                const float4 sv = *reinterpret_cast<const float4*>(ss + k * QPAD + qt * 4);
                const ulonglong2 mA = *reinterpret_cast<const ulonglong2*>(ms + k * TPAD + tt * 12);
                const ulonglong2 mB = *reinterpret_cast<const ulonglong2*>(ms + k * TPAD + tt * 12 + 4);
                const unsigned long long mC = *reinterpret_cast<const unsigned long long*>(ms + k * TPAD + tt * 12 + 8);
                const unsigned long long mp[5] = { mA.x, mA.y, mB.x, mB.y, mC };
                const float xa[4] = { xv.x, xv.y, xv.z, xv.w };
                const float sa[4] = { sv.x, sv.y, sv.z, sv.w };
                #pragma unroll
                for (int i = 0; i < 4; i++) {
                    unsigned long long xq = dup2(xa[i]);
                    unsigned long long sq = dup2(sa[i]);
                    #pragma unroll
                    for (int p = 0; p < 5; p++) {
                        fma2(a1[i][p], xq, mp[p]);
                        fma2(a2[i][p], sq, mp[p]);
                    }
                }
            }
        }
        __syncthreads();
    }

    // ---- epilogue: partial-accumulator reduction via atomics ----
    if (comp) {
        #pragma unroll
        for (int i = 0; i < 4; i++) {
            int q = qt * 4 + i;
            #pragma unroll
            for (int p = 0; p < 5; p++) {
                int t = tt * 10 + 2 * p;
                float2 v1 = unpk(a1[i][p]);
                float2 v2 = unpk(a2[i][p]);
                size_t o = (size_t)(b * Q_ + q) * T_ + t;
                atomicAdd(&g_D1[o],     v1.x);
                atomicAdd(&g_D1[o + 1], v1.y);
                atomicAdd(&g_D2[o],     v2.x);
                atomicAdd(&g_D2[o + 1], v2.y);
            }
        }
    }
    #pragma unroll
    for (int j = 0; j < 7; j++) {
        int s = tid + 128 * j;
        if (s < Q_ * 8) {
            int row = s >> 3;
            atomicAdd(&g_Sneg[b * Q_ + row], aSP[j]);
            atomicAdd(&g_Ssig[b * Q_ + row], aSG[j]);
        }
    }
    #pragma unroll
    for (int j = 0; j < 4; j++) {
        int s = tid + 128 * j;
        if (s < T_ * 8) atomicAdd(&g_Sm[b * T_ + (s >> 3)], aM[j]);
    }
}

// ---------------- kernel 2: combine + class cost ----------------
__global__ void combine_kernel(const float* __restrict__ clsq,
                               const int* __restrict__ labw,
                               float* __restrict__ out)
{
    int idx = blockIdx.x * blockDim.x + threadIdx.x;
    if (idx >= B_*Q_*T_) return;
    int t = idx % T_;
    int q = (idx / T_) % Q_;
    int b = idx / (Q_*T_);

    int li  = b * T_ + t;
    int lbl = g_is64 ? labw[2 * li] : labw[li];

    const float* cl = clsq + (size_t)(b * Q_ + q) * L_;
    float mx = cl[0];
    #pragma unroll
    for (int c = 1; c < L_; c++) mx = fmaxf(mx, cl[c]);
    float s = 0.f;
    #pragma unroll
    for (int c = 0; c < L_; c++) s += __expf(cl[c] - mx);
    float prob = __expf(cl[lbl] - mx) / s;

    float Sneg = g_Sneg[b * Q_ + q];
    float Ssig = g_Ssig[b * Q_ + q];
    float Sm   = g_Sm[li];
    float D1   = g_D1[idx];
    float D2   = g_D2[idx];

    float cmask = (Sneg - D1) * (1.0f / (float)G_);
    float cdice = 1.0f - (2.0f * D2 + 1.0f) / (Ssig + Sm + 1.0f);
    out[idx] = cmask - prob + cdice;
}

// ---------------- launch ----------------
extern "C" void kernel_launch(void* const* d_in, const int* in_sizes, int n_in,
                              void* d_out, int out_size)
{
    const float* x   = (const float*)d_in[0];   // masks_queries_logits [16,100,16384]
    const float* cq  = (const float*)d_in[1];   // class_queries_logits [16,100,21]
    const float* m   = (const float*)d_in[2];   // mask_labels [16,50,16384]
    const int*   lab = (const int*)d_in[3];     // class_labels [16,50] int32 or int64

    zero_detect_kernel<<<(B_*Q_*T_ + 255) / 256, 256>>>(lab);

    dim3 grid(NCHUNK, B_);
    pm_main_kernel<<<grid, 128>>>(x, m);

    combine_kernel<<<(B_*Q_*T_ + 255) / 256, 256>>>(cq, lab, (float*)d_out);
}

// round 3
// speedup vs baseline: 2.4482x; 2.4482x over previous
#include <cuda_runtime.h>
#include <cuda_bf16.h>
#include <stdint.h>

#define B_ 16
#define Q_ 100
#define G_ 16384
#define T_ 50
#define L_ 21
#define NCH 9
#define KB 64          // k elements per stage
#define MP 112         // padded M (7 warps x 16)
#define NP 56          // padded N (7 n-tiles x 8)
#define NT 224         // threads (7 warps)

// ---------------- device scratch (module statics, allocation-free) ----------------
__device__ float g_P1[B_*NCH*MP*NP];     // partial dot(x, m)
__device__ float g_P2[B_*NCH*MP*NP];     // partial dot(sig(x), m)
__device__ float g_SnegP[B_*NCH*Q_];     // partial softplus row sums
__device__ float g_SsigP[B_*NCH*Q_];     // partial sigmoid row sums
__device__ float g_SmP[B_*NCH*T_];       // partial mask row sums

// ---------------- helpers ----------------
__device__ __forceinline__ uint32_t smem_u32(const void* p) {
    uint32_t a;
    asm("{ .reg .u64 t; cvta.to.shared.u64 t, %1; cvt.u32.u64 %0, t; }"
        : "=r"(a) : "l"(p));
    return a;
}
__device__ __forceinline__ uint32_t bf2(float lo, float hi) {
    uint32_t r;
    asm("cvt.rn.bf16x2.f32 %0, %1, %2;" : "=r"(r) : "f"(hi), "f"(lo));
    return r;
}
__device__ __forceinline__ float fast_tanh(float x) {
    float r;
    asm("tanh.approx.f32 %0, %1;" : "=f"(r) : "f"(x));
    return r;
}
__device__ __forceinline__ float fast_lg2(float x) {
    float r;
    asm("lg2.approx.f32 %0, %1;" : "=f"(r) : "f"(x));
    return r;
}
#define LDSM4(r0,r1,r2,r3,addr) \
    asm volatile("ldmatrix.sync.aligned.m8n8.x4.shared.b16 {%0,%1,%2,%3}, [%4];" \
        : "=r"(r0),"=r"(r1),"=r"(r2),"=r"(r3) : "r"(addr))
#define LDSM2(r0,r1,addr) \
    asm volatile("ldmatrix.sync.aligned.m8n8.x2.shared.b16 {%0,%1}, [%2];" \
        : "=r"(r0),"=r"(r1) : "r"(addr))
#define MMA16816(d,a,b) \
    asm volatile("mma.sync.aligned.m16n8k16.row.col.f32.bf16.bf16.f32 " \
        "{%0,%1,%2,%3},{%4,%5,%6,%7},{%8,%9},{%0,%1,%2,%3};" \
        : "+f"((d)[0]),"+f"((d)[1]),"+f"((d)[2]),"+f"((d)[3]) \
        : "r"((a)[0]),"r"((a)[1]),"r"((a)[2]),"r"((a)[3]),"r"((b)[0]),"r"((b)[1]))

// ---------------- kernel 1: fused convert + dual HMMA GEMM ----------------
// grid = (NCH, B_), block = 224. CTA tile: M=112 (q), N=56 (t), K-chunk.
__global__ void __launch_bounds__(NT, 1)
pm_mma_kernel(const float* __restrict__ xg, const float* __restrict__ mg)
{
    __shared__ __align__(1024) __nv_bfloat16 sA[MP*KB];   // x    14336 B
    __shared__ __align__(1024) __nv_bfloat16 sS[MP*KB];   // sig  14336 B
    __shared__ __align__(1024) __nv_bfloat16 sB[NP*KB];   // m     7168 B

    const int b   = blockIdx.y;
    const int c   = blockIdx.x;
    const int tid = threadIdx.x;
    const int wid = tid >> 5;
    const int lid = tid & 31;

    // K split: 256 KB-units over 9 chunks -> 4x29 + 5x28
    const int nu = 28 + (c < 4 ? 1 : 0);
    const int u0 = c * 28 + (c < 4 ? c : 4);

    // zero smem once (pad rows stay zero; loop never writes them)
    for (int i = tid; i < MP*KB/8; i += NT) {
        reinterpret_cast<uint4*>(sA)[i] = make_uint4(0,0,0,0);
        reinterpret_cast<uint4*>(sS)[i] = make_uint4(0,0,0,0);
    }
    for (int i = tid; i < NP*KB/8; i += NT)
        reinterpret_cast<uint4*>(sB)[i] = make_uint4(0,0,0,0);
    __syncthreads();

    const uint32_t sA32 = smem_u32(sA);
    const uint32_t sS32 = smem_u32(sS);
    const uint32_t sB32 = smem_u32(sB);

    // ---- ldmatrix address precompute ----
    const int mbase = wid * 16;
    const int arow  = mbase + (lid & 15);
    const uint32_t aoff  = (uint32_t)(arow * 128);
    const uint32_t axor  = (uint32_t)((arow & 7) << 4);
    const uint32_t akb0  = (uint32_t)((lid >> 4) << 4);      // 0 | 16
    const int bg = lid >> 3, br = lid & 7;
    const uint32_t bxor = (uint32_t)(br << 4);
    const uint32_t bkb0 = (uint32_t)((bg & 1) << 4);

    // ---- loader slot precompute ----
    const float* xb = xg + (size_t)b * Q_ * G_;
    const float* mb = mg + (size_t)b * T_ * G_;
    int xrow[8], xc4[8]; bool xact[8];
    #pragma unroll
    for (int j = 0; j < 8; j++) {
        int sl = tid + NT * j;
        xact[j] = sl < Q_ * (KB/4);
        xrow[j] = sl >> 4; xc4[j] = sl & 15;
    }
    int mrow[4], mc4[4]; bool mact[4];
    #pragma unroll
    for (int j = 0; j < 4; j++) {
        int sl = tid + NT * j;
        mact[j] = sl < T_ * (KB/4);
        mrow[j] = sl >> 4; mc4[j] = sl & 15;
    }

    float c1[7][4], c2[7][4];
    #pragma unroll
    for (int j = 0; j < 7; j++)
        #pragma unroll
        for (int u = 0; u < 4; u++) { c1[j][u] = 0.f; c2[j][u] = 0.f; }
    float aSP[8], aSG[8], aM[4];
    #pragma unroll
    for (int j = 0; j < 8; j++) { aSP[j] = 0.f; aSG[j] = 0.f; }
    #pragma unroll
    for (int j = 0; j < 4; j++) aM[j] = 0.f;

    for (int s = 0; s < nu; s++) {
        const int k0 = (u0 + s) * KB;

        // ---- LDG (overlaps previous stage's HMMA) ----
        float4 vx[8], vm[4];
        #pragma unroll
        for (int j = 0; j < 8; j++)
            if (xact[j])
                vx[j] = *reinterpret_cast<const float4*>(
                    xb + (size_t)xrow[j] * G_ + k0 + xc4[j] * 4);
        #pragma unroll
        for (int j = 0; j < 4; j++)
            if (mact[j])
                vm[j] = *reinterpret_cast<const float4*>(
                    mb + (size_t)mrow[j] * G_ + k0 + mc4[j] * 4);

        // ---- convert: sigmoid via tanh (1 MUFU), softplus via lg2 (1 MUFU) ----
        uint32_t pxa[8][2], pxs[8][2], pmm[4][2];
        #pragma unroll
        for (int j = 0; j < 8; j++) {
            if (!xact[j]) continue;
            float f[4] = { vx[j].x, vx[j].y, vx[j].z, vx[j].w };
            float sg[4];
            #pragma unroll
            for (int u = 0; u < 4; u++) {
                float x    = f[u];
                float t    = fast_tanh(0.5f * x);
                float sig  = fmaf(0.5f, t, 0.5f);
                float siga = fmaf(0.5f, fabsf(t), 0.5f);   // sigmoid(|x|)
                sg[u] = sig;
                aSG[j] += sig;
                aSP[j] += fmaxf(x, 0.f) - 0.69314718056f * fast_lg2(siga);
            }
            pxa[j][0] = bf2(f[0], f[1]);   pxa[j][1] = bf2(f[2], f[3]);
            pxs[j][0] = bf2(sg[0], sg[1]); pxs[j][1] = bf2(sg[2], sg[3]);
        }
        #pragma unroll
        for (int j = 0; j < 4; j++) {
            if (!mact[j]) continue;
            aM[j] += vm[j].x + vm[j].y + vm[j].z + vm[j].w;
            pmm[j][0] = bf2(vm[j].x, vm[j].y);
            pmm[j][1] = bf2(vm[j].z, vm[j].w);
        }

        __syncthreads();   // previous stage's ldmatrix reads complete

        // ---- STS with SW128 swizzle ----
        #pragma unroll
        for (int j = 0; j < 8; j++) {
            if (!xact[j]) continue;
            uint32_t off = (uint32_t)(xrow[j] * 128)
                         + (uint32_t)((xc4[j] * 8) ^ ((xrow[j] & 7) << 4));
            *reinterpret_cast<uint2*>(reinterpret_cast<char*>(sA) + off) =
                make_uint2(pxa[j][0], pxa[j][1]);
            *reinterpret_cast<uint2*>(reinterpret_cast<char*>(sS) + off) =
                make_uint2(pxs[j][0], pxs[j][1]);
        }
        #pragma unroll
        for (int j = 0; j < 4; j++) {
            if (!mact[j]) continue;
            uint32_t off = (uint32_t)(mrow[j] * 128)
                         + (uint32_t)((mc4[j] * 8) ^ ((mrow[j] & 7) << 4));
            *reinterpret_cast<uint2*>(reinterpret_cast<char*>(sB) + off) =
                make_uint2(pmm[j][0], pmm[j][1]);
        }
        __syncthreads();

        // ---- MMA: 4 k-steps x 7 n-tiles x 2 gemms ----
        #pragma unroll
        for (int ks = 0; ks < 4; ks++) {
            const uint32_t akb = (uint32_t)(ks * 32) + akb0;
            const uint32_t aad = aoff + (akb ^ axor);
            uint32_t ax[4], as2[4];
            LDSM4(ax[0],  ax[1],  ax[2],  ax[3],  sA32 + aad);
            LDSM4(as2[0], as2[1], as2[2], as2[3], sS32 + aad);

            uint32_t bf[7][2];
            #pragma unroll
            for (int p = 0; p < 3; p++) {
                int j = p * 2;
                int row = (j + (bg >> 1)) * 8 + br;
                uint32_t kb = (uint32_t)(ks * 32) + bkb0;
                uint32_t ad = (uint32_t)(row * 128) + (kb ^ bxor);
                LDSM4(bf[j][0], bf[j][1], bf[j+1][0], bf[j+1][1], sB32 + ad);
            }
            {   // n-tile 6 (x2: threads 0-15 supply addresses)
                int row = 48 + br;
                uint32_t kb = (uint32_t)(ks * 32) + (uint32_t)((bg & 1) << 4);
                uint32_t ad = (uint32_t)(row * 128) + (kb ^ bxor);
                LDSM2(bf[6][0], bf[6][1], sB32 + ad);
            }
            #pragma unroll
            for (int j = 0; j < 7; j++) {
                MMA16816(c1[j], ax,  bf[j]);
                MMA16816(c2[j], as2, bf[j]);
            }
        }
    }

    // ---- row-stat reduction (16 lanes per row -> shfl) ----
    #pragma unroll
    for (int j = 0; j < 8; j++) {
        if (!xact[j]) continue;          // uniform per warp (boundaries warp-aligned)
        float v1 = aSP[j], v2 = aSG[j];
        #pragma unroll
        for (int o = 8; o > 0; o >>= 1) {
            v1 += __shfl_xor_sync(0xffffffffu, v1, o);
            v2 += __shfl_xor_sync(0xffffffffu, v2, o);
        }
        if ((lid & 15) == 0) {
            g_SnegP[(b * NCH + c) * Q_ + xrow[j]] = v1;
            g_SsigP[(b * NCH + c) * Q_ + xrow[j]] = v2;
        }
    }
    #pragma unroll
    for (int j = 0; j < 4; j++) {
        if (!mact[j]) continue;
        float v = aM[j];
        #pragma unroll
        for (int o = 8; o > 0; o >>= 1)
            v += __shfl_xor_sync(0xffffffffu, v, o);
        if ((lid & 15) == 0)
            g_SmP[(b * NCH + c) * T_ + mrow[j]] = v;
    }

    // ---- C epilogue: direct stores (disjoint per CTA, padded layout) ----
    {
        const int r0 = mbase + (lid >> 2);
        const int cb = (lid & 3) * 2;
        float* p1 = g_P1 + ((size_t)((b * NCH + c) * MP + r0)) * NP;
        float* p2 = g_P2 + ((size_t)((b * NCH + c) * MP + r0)) * NP;
        #pragma unroll
        for (int j = 0; j < 7; j++) {
            int col = j * 8 + cb;
            *reinterpret_cast<float2*>(p1 + col)          = make_float2(c1[j][0], c1[j][1]);
            *reinterpret_cast<float2*>(p1 + 8*NP + col)   = make_float2(c1[j][2], c1[j][3]);
            *reinterpret_cast<float2*>(p2 + col)          = make_float2(c2[j][0], c2[j][1]);
            *reinterpret_cast<float2*>(p2 + 8*NP + col)   = make_float2(c2[j][2], c2[j][3]);
        }
    }
}

// ---------------- kernel 2: reduce partials + class cost ----------------
__global__ void combine_kernel(const float* __restrict__ clsq,
                               const int* __restrict__ labw,
                               float* __restrict__ out)
{
    int idx = blockIdx.x * blockDim.x + threadIdx.x;
    if (idx >= B_*Q_*T_) return;
    int t = idx % T_;
    int q = (idx / T_) % Q_;
    int b = idx / (Q_*T_);

    // label dtype detect: int64 high words of labels 0..7 are all zero;
    // for int32 that's 8 random labels in [0,21) all == 0 (p ~ 2.6e-11).
    bool is64 = true;
    #pragma unroll
    for (int j = 0; j < 8; j++) is64 &= (labw[2*j + 1] == 0);
    int li  = b * T_ + t;
    int lbl = is64 ? labw[2 * li] : labw[li];

    const float* cl = clsq + (size_t)(b * Q_ + q) * L_;
    float mx = cl[0];
    #pragma unroll
    for (int k = 1; k < L_; k++) mx = fmaxf(mx, cl[k]);
    float ssum = 0.f;
    #pragma unroll
    for (int k = 0; k < L_; k++) ssum += __expf(cl[k] - mx);
    float prob = __expf(cl[lbl] - mx) / ssum;

    float D1 = 0.f, D2 = 0.f, Sneg = 0.f, Ssig = 0.f, Sm = 0.f;
    #pragma unroll
    for (int c = 0; c < NCH; c++) {
        size_t o = ((size_t)((b * NCH + c) * MP + q)) * NP + t;
        D1 += g_P1[o];
        D2 += g_P2[o];
        Sneg += g_SnegP[(b * NCH + c) * Q_ + q];
        Ssig += g_SsigP[(b * NCH + c) * Q_ + q];
        Sm   += g_SmP[(b * NCH + c) * T_ + t];
    }

    float cmask = (Sneg - D1) * (1.0f / (float)G_);
    float cdice = 1.0f - (2.0f * D2 + 1.0f) / (Ssig + Sm + 1.0f);
    out[idx] = cmask - prob + cdice;
}

// ---------------- launch ----------------
extern "C" void kernel_launch(void* const* d_in, const int* in_sizes, int n_in,
                              void* d_out, int out_size)
{
    const float* x   = (const float*)d_in[0];   // [16,100,16384] f32
    const float* cq  = (const float*)d_in[1];   // [16,100,21]    f32
    const float* m   = (const float*)d_in[2];   // [16,50,16384]  f32
    const int*   lab = (const int*)d_in[3];     // [16,50] labels

    dim3 grid(NCH, B_);
    pm_mma_kernel<<<grid, NT>>>(x, m);

    combine_kernel<<<(B_*Q_*T_ + 255) / 256, 256>>>(cq, lab, (float*)d_out);
}